// round 1
// baseline (speedup 1.0000x reference)
#include <cuda_runtime.h>
#include <math.h>

#define D 128
#define MAXS 65536
#define MAXN 8192

// Scratch (device globals — no runtime allocation)
__device__ float g_ztxt[MAXN * D];              // normalized text features
__device__ float g_A[MAXN * D];                 // selected+normalized image rows (zimg_sel)
__device__ float g_inv[MAXS];                   // 1/(||img||+1e-12) per image
__device__ unsigned long long g_seg[MAXN];      // packed (pot_bits<<32)|img_idx, atomicMin
__device__ float g_validf[MAXN];                // 1.0 if text has >=1 image
__device__ int g_nvalid;
__device__ double g_sum;

// ---------------- Phase 0: reset scratch (graph replays must be deterministic)
__global__ void k_init(int n) {
    int i = blockIdx.x * blockDim.x + threadIdx.x;
    if (i < n) g_seg[i] = ~0ull;
    if (i == 0) { g_sum = 0.0; g_nvalid = 0; }
}

// ---------------- Phase 1: normalize text features (one warp per row)
__global__ void k_norm_txt(const float* __restrict__ txt, int n) {
    int w = (blockIdx.x * blockDim.x + threadIdx.x) >> 5;
    int lane = threadIdx.x & 31;
    if (w >= n) return;
    float4 v = reinterpret_cast<const float4*>(txt + (size_t)w * D)[lane];
    float ss = v.x*v.x + v.y*v.y + v.z*v.z + v.w*v.w;
    #pragma unroll
    for (int o = 16; o > 0; o >>= 1) ss += __shfl_xor_sync(0xffffffffu, ss, o);
    float inv = 1.0f / (sqrtf(ss) + 1e-12f);
    float4 r = make_float4(v.x*inv, v.y*inv, v.z*inv, v.w*inv);
    reinterpret_cast<float4*>(g_ztxt + (size_t)w * D)[lane] = r;
}

// ---------------- Phase 2: per-image tp logit + segmented argmin (one warp per image)
__global__ void k_img(const float* __restrict__ img, const int* __restrict__ key,
                      const float* __restrict__ sp, const float* __restrict__ bp, int s) {
    int w = (blockIdx.x * blockDim.x + threadIdx.x) >> 5;
    int lane = threadIdx.x & 31;
    if (w >= s) return;
    float4 v = reinterpret_cast<const float4*>(img + (size_t)w * D)[lane];
    int k = key[w];
    float4 t = reinterpret_cast<const float4*>(g_ztxt + (size_t)k * D)[lane];
    float ss = v.x*v.x + v.y*v.y + v.z*v.z + v.w*v.w;
    float dt = v.x*t.x + v.y*t.y + v.z*t.z + v.w*t.w;
    #pragma unroll
    for (int o = 16; o > 0; o >>= 1) {
        ss += __shfl_xor_sync(0xffffffffu, ss, o);
        dt += __shfl_xor_sync(0xffffffffu, dt, o);
    }
    if (lane == 0) {
        float inv = 1.0f / (sqrtf(ss) + 1e-12f);
        g_inv[w] = inv;
        float tp = fmaf(dt * inv, *sp, *bp);
        // pot = softplus(-tp), precise path (selection must match reference)
        float t0 = -tp;
        float pot = fmaxf(t0, 0.0f) + log1pf(expf(-fabsf(t0)));
        // non-negative float bits order as unsigned; lexicographic (pot, idx) min
        unsigned long long pk =
            ((unsigned long long)__float_as_uint(pot) << 32) | (unsigned)w;
        atomicMin(&g_seg[k], pk);
    }
}

// ---------------- Phase 3: gather best image per text, normalize, mark valid
__global__ void k_gather(const float* __restrict__ img, int n) {
    int w = (blockIdx.x * blockDim.x + threadIdx.x) >> 5;
    int lane = threadIdx.x & 31;
    if (w >= n) return;
    unsigned long long sv = g_seg[w];
    bool valid = (sv != ~0ull);
    float4 o = make_float4(0.f, 0.f, 0.f, 0.f);
    if (valid) {
        unsigned best = (unsigned)(sv & 0xffffffffu);
        float inv = g_inv[best];
        float4 v = reinterpret_cast<const float4*>(img + (size_t)best * D)[lane];
        o = make_float4(v.x*inv, v.y*inv, v.z*inv, v.w*inv);
    }
    reinterpret_cast<float4*>(g_A + (size_t)w * D)[lane] = o;
    if (lane == 0) {
        g_validf[w] = valid ? 1.0f : 0.0f;
        if (valid) atomicAdd(&g_nvalid, 1);
    }
}

// ---------------- Phase 4: fused GEMM (A @ ztxt^T) + masked softplus-sum epilogue
// 128x128 block tile, 8x8 per thread, BK=32, fp32 CUDA cores.
__global__ void __launch_bounds__(256, 2)
k_gemm_loss(const float* __restrict__ sp, const float* __restrict__ bp, int n) {
    __shared__ __align__(16) float Ast[32][132];   // [k][m], padded stride
    __shared__ __align__(16) float Bst[32][132];   // [k][n]
    __shared__ float red[256];

    const float scale = *sp, bias = *bp;
    int tid = threadIdx.x;
    int tx = tid & 15, ty = tid >> 4;
    int bm = blockIdx.y, bn = blockIdx.x;
    const float* Ag = g_A    + (size_t)bm * 128 * D;
    const float* Bg = g_ztxt + (size_t)bn * 128 * D;

    float acc[8][8];
    #pragma unroll
    for (int i = 0; i < 8; i++)
        #pragma unroll
        for (int j = 0; j < 8; j++) acc[i][j] = 0.f;

    for (int kc = 0; kc < D; kc += 32) {
        // cooperative load+transpose: 128 rows x 32 k floats per side
        #pragma unroll
        for (int i = 0; i < 4; i++) {
            int idx4 = tid + i * 256;     // 0..1023 float4 slots
            int row  = idx4 >> 3;         // 0..127
            int k4   = idx4 & 7;          // 0..7
            float4 va = reinterpret_cast<const float4*>(Ag + row * D + kc)[k4];
            float4 vb = reinterpret_cast<const float4*>(Bg + row * D + kc)[k4];
            Ast[k4*4+0][row] = va.x; Ast[k4*4+1][row] = va.y;
            Ast[k4*4+2][row] = va.z; Ast[k4*4+3][row] = va.w;
            Bst[k4*4+0][row] = vb.x; Bst[k4*4+1][row] = vb.y;
            Bst[k4*4+2][row] = vb.z; Bst[k4*4+3][row] = vb.w;
        }
        __syncthreads();
        #pragma unroll
        for (int k = 0; k < 32; k++) {
            float4 a0 = *reinterpret_cast<const float4*>(&Ast[k][ty*8]);
            float4 a1 = *reinterpret_cast<const float4*>(&Ast[k][ty*8+4]);
            float4 b0 = *reinterpret_cast<const float4*>(&Bst[k][tx*8]);
            float4 b1 = *reinterpret_cast<const float4*>(&Bst[k][tx*8+4]);
            float a[8] = {a0.x,a0.y,a0.z,a0.w,a1.x,a1.y,a1.z,a1.w};
            float b[8] = {b0.x,b0.y,b0.z,b0.w,b1.x,b1.y,b1.z,b1.w};
            #pragma unroll
            for (int i = 0; i < 8; i++)
                #pragma unroll
                for (int j = 0; j < 8; j++)
                    acc[i][j] = fmaf(a[i], b[j], acc[i][j]);
        }
        __syncthreads();
    }

    // epilogue: terms = softplus(+-logits), masked by valid_i & valid_j
    int gi0 = bm * 128 + ty * 8;
    int gj0 = bn * 128 + tx * 8;
    float vr[8], vc[8];
    #pragma unroll
    for (int i = 0; i < 8; i++) vr[i] = g_validf[gi0 + i];
    #pragma unroll
    for (int j = 0; j < 8; j++) vc[j] = g_validf[gj0 + j];

    float sum = 0.f;
    #pragma unroll
    for (int i = 0; i < 8; i++) {
        #pragma unroll
        for (int j = 0; j < 8; j++) {
            float x = fmaf(acc[i][j], scale, bias);       // logit
            float t = (gi0 + i == gj0 + j) ? -x : x;      // softplus argument
            float m = fmaxf(t, 0.f);
            float r = __expf(-fabsf(t));
            float spv;
            if (r < 0.25f) {
                // m + log1p(r), 5-term alternating series (|err| <= r^6/6 < 4.1e-5)
                spv = fmaf(r, fmaf(r, fmaf(r, fmaf(r, fmaf(r, 0.2f, -0.25f),
                          0.33333334f), -0.5f), 1.0f), m);
            } else {
                spv = m + log1pf(r);
            }
            sum += spv * vr[i] * vc[j];
        }
    }

    red[tid] = sum;
    __syncthreads();
    #pragma unroll
    for (int st = 128; st > 0; st >>= 1) {
        if (tid < st) red[tid] += red[tid + st];
        __syncthreads();
    }
    if (tid == 0) atomicAdd(&g_sum, (double)red[0]);
}

// ---------------- Phase 5: finalize
__global__ void k_final(float* out) {
    int nv = g_nvalid;
    if (nv < 1) nv = 1;
    out[0] = (float)(g_sum / (double)nv);
}

extern "C" void kernel_launch(void* const* d_in, const int* in_sizes, int n_in,
                              void* d_out, int out_size) {
    const float* img = (const float*)d_in[0];
    const float* txt = (const float*)d_in[1];
    const int*   key = (const int*)d_in[2];
    const float* sc  = (const float*)d_in[3];
    const float* bi  = (const float*)d_in[4];
    int s = in_sizes[2];          // 65536
    int n = in_sizes[1] / D;      // 8192

    k_init<<<(n + 255) / 256, 256>>>(n);
    k_norm_txt<<<(n * 32 + 255) / 256, 256>>>(txt, n);
    k_img<<<(s * 32 + 255) / 256, 256>>>(img, key, sc, bi, s);
    k_gather<<<(n * 32 + 255) / 256, 256>>>(img, n);
    dim3 grid(n / 128, n / 128);
    k_gemm_loss<<<grid, 256>>>(sc, bi, n);
    k_final<<<1, 1>>>((float*)d_out);
}

// round 2
// speedup vs baseline: 1.0256x; 1.0256x over previous
#include <cuda_runtime.h>
#include <math.h>

#define D 128
#define MAXS 65536
#define MAXN 8192

// Scratch (device globals — no runtime allocation)
__device__ float g_ztxt[MAXN * D];              // normalized text features
__device__ float g_A[MAXN * D];                 // selected+normalized image rows (zimg_sel)
__device__ float g_inv[MAXS];                   // 1/(||img||+1e-12) per image
__device__ unsigned long long g_seg[MAXN];      // packed (pot_bits<<32)|img_idx, atomicMin
__device__ float g_validf[MAXN];                // 1.0 if text has >=1 image
__device__ int g_nvalid;
__device__ double g_sum;

// ---------------- Phase 0: reset scratch (graph replays must be deterministic)
__global__ void k_init(int n) {
    int i = blockIdx.x * blockDim.x + threadIdx.x;
    if (i < n) g_seg[i] = ~0ull;
    if (i == 0) { g_sum = 0.0; g_nvalid = 0; }
}

// ---------------- Phase 1: normalize text features (one warp per row)
__global__ void k_norm_txt(const float* __restrict__ txt, int n) {
    int w = (blockIdx.x * blockDim.x + threadIdx.x) >> 5;
    int lane = threadIdx.x & 31;
    if (w >= n) return;
    float4 v = reinterpret_cast<const float4*>(txt + (size_t)w * D)[lane];
    float ss = v.x*v.x + v.y*v.y + v.z*v.z + v.w*v.w;
    #pragma unroll
    for (int o = 16; o > 0; o >>= 1) ss += __shfl_xor_sync(0xffffffffu, ss, o);
    float inv = 1.0f / (sqrtf(ss) + 1e-12f);
    float4 r = make_float4(v.x*inv, v.y*inv, v.z*inv, v.w*inv);
    reinterpret_cast<float4*>(g_ztxt + (size_t)w * D)[lane] = r;
}

// ---------------- Phase 2: per-image tp logit + segmented argmin (one warp per image)
__global__ void k_img(const float* __restrict__ img, const int* __restrict__ key,
                      const float* __restrict__ sp, const float* __restrict__ bp, int s) {
    int w = (blockIdx.x * blockDim.x + threadIdx.x) >> 5;
    int lane = threadIdx.x & 31;
    if (w >= s) return;
    float4 v = reinterpret_cast<const float4*>(img + (size_t)w * D)[lane];
    int k = key[w];
    float4 t = reinterpret_cast<const float4*>(g_ztxt + (size_t)k * D)[lane];
    float ss = v.x*v.x + v.y*v.y + v.z*v.z + v.w*v.w;
    float dt = v.x*t.x + v.y*t.y + v.z*t.z + v.w*t.w;
    #pragma unroll
    for (int o = 16; o > 0; o >>= 1) {
        ss += __shfl_xor_sync(0xffffffffu, ss, o);
        dt += __shfl_xor_sync(0xffffffffu, dt, o);
    }
    if (lane == 0) {
        float inv = 1.0f / (sqrtf(ss) + 1e-12f);
        g_inv[w] = inv;
        float tp = fmaf(dt * inv, *sp, *bp);
        // pot = softplus(-tp), precise path (selection must match reference)
        float t0 = -tp;
        float pot = fmaxf(t0, 0.0f) + log1pf(expf(-fabsf(t0)));
        // non-negative float bits order as unsigned; lexicographic (pot, idx) min
        unsigned long long pk =
            ((unsigned long long)__float_as_uint(pot) << 32) | (unsigned)w;
        atomicMin(&g_seg[k], pk);
    }
}

// ---------------- Phase 3: gather best image per text, normalize, mark valid
__global__ void k_gather(const float* __restrict__ img, int n) {
    int w = (blockIdx.x * blockDim.x + threadIdx.x) >> 5;
    int lane = threadIdx.x & 31;
    if (w >= n) return;
    unsigned long long sv = g_seg[w];
    bool valid = (sv != ~0ull);
    float4 o = make_float4(0.f, 0.f, 0.f, 0.f);
    if (valid) {
        unsigned best = (unsigned)(sv & 0xffffffffu);
        float inv = g_inv[best];
        float4 v = reinterpret_cast<const float4*>(img + (size_t)best * D)[lane];
        o = make_float4(v.x*inv, v.y*inv, v.z*inv, v.w*inv);
    }
    reinterpret_cast<float4*>(g_A + (size_t)w * D)[lane] = o;
    if (lane == 0) {
        g_validf[w] = valid ? 1.0f : 0.0f;
        if (valid) atomicAdd(&g_nvalid, 1);
    }
}

// ---------------- Phase 4: fused GEMM (A @ ztxt^T) + masked softplus-sum epilogue
// 128x128 block tile, 8x8 per thread, BK=32, fp32 CUDA cores.
__global__ void __launch_bounds__(256, 2)
k_gemm_loss(const float* __restrict__ sp, const float* __restrict__ bp, int n) {
    __shared__ __align__(16) float Ast[32][132];   // [k][m], padded stride
    __shared__ __align__(16) float Bst[32][132];   // [k][n]
    __shared__ float red[256];

    const float scale = *sp, bias = *bp;
    int tid = threadIdx.x;
    int tx = tid & 15, ty = tid >> 4;
    int bm = blockIdx.y, bn = blockIdx.x;
    const float* Ag = g_A    + (size_t)bm * 128 * D;
    const float* Bg = g_ztxt + (size_t)bn * 128 * D;

    float acc[8][8];
    #pragma unroll
    for (int i = 0; i < 8; i++)
        #pragma unroll
        for (int j = 0; j < 8; j++) acc[i][j] = 0.f;

    for (int kc = 0; kc < D; kc += 32) {
        // cooperative load+transpose: 128 rows x 32 k floats per side
        #pragma unroll
        for (int i = 0; i < 4; i++) {
            int idx4 = tid + i * 256;     // 0..1023 float4 slots
            int row  = idx4 >> 3;         // 0..127
            int k4   = idx4 & 7;          // 0..7
            float4 va = reinterpret_cast<const float4*>(Ag + row * D + kc)[k4];
            float4 vb = reinterpret_cast<const float4*>(Bg + row * D + kc)[k4];
            Ast[k4*4+0][row] = va.x; Ast[k4*4+1][row] = va.y;
            Ast[k4*4+2][row] = va.z; Ast[k4*4+3][row] = va.w;
            Bst[k4*4+0][row] = vb.x; Bst[k4*4+1][row] = vb.y;
            Bst[k4*4+2][row] = vb.z; Bst[k4*4+3][row] = vb.w;
        }
        __syncthreads();
        #pragma unroll
        for (int k = 0; k < 32; k++) {
            float4 a0 = *reinterpret_cast<const float4*>(&Ast[k][ty*8]);
            float4 a1 = *reinterpret_cast<const float4*>(&Ast[k][ty*8+4]);
            float4 b0 = *reinterpret_cast<const float4*>(&Bst[k][tx*8]);
            float4 b1 = *reinterpret_cast<const float4*>(&Bst[k][tx*8+4]);
            float a[8] = {a0.x,a0.y,a0.z,a0.w,a1.x,a1.y,a1.z,a1.w};
            float b[8] = {b0.x,b0.y,b0.z,b0.w,b1.x,b1.y,b1.z,b1.w};
            #pragma unroll
            for (int i = 0; i < 8; i++)
                #pragma unroll
                for (int j = 0; j < 8; j++)
                    acc[i][j] = fmaf(a[i], b[j], acc[i][j]);
        }
        __syncthreads();
    }

    // epilogue: terms = softplus(+-logits), masked by valid_i & valid_j
    int gi0 = bm * 128 + ty * 8;
    int gj0 = bn * 128 + tx * 8;
    float vr[8], vc[8];
    #pragma unroll
    for (int i = 0; i < 8; i++) vr[i] = g_validf[gi0 + i];
    #pragma unroll
    for (int j = 0; j < 8; j++) vc[j] = g_validf[gj0 + j];

    float sum = 0.f;
    #pragma unroll
    for (int i = 0; i < 8; i++) {
        #pragma unroll
        for (int j = 0; j < 8; j++) {
            float x = fmaf(acc[i][j], scale, bias);       // logit
            float t = (gi0 + i == gj0 + j) ? -x : x;      // softplus argument
            float m = fmaxf(t, 0.f);
            float r = __expf(-fabsf(t));
            float spv;
            if (r < 0.25f) {
                // m + log1p(r), 5-term alternating series (|err| <= r^6/6 < 4.1e-5)
                spv = fmaf(r, fmaf(r, fmaf(r, fmaf(r, fmaf(r, 0.2f, -0.25f),
                          0.33333334f), -0.5f), 1.0f), m);
            } else {
                spv = m + log1pf(r);
            }
            sum += spv * vr[i] * vc[j];
        }
    }

    red[tid] = sum;
    __syncthreads();
    #pragma unroll
    for (int st = 128; st > 0; st >>= 1) {
        if (tid < st) red[tid] += red[tid + st];
        __syncthreads();
    }
    if (tid == 0) atomicAdd(&g_sum, (double)red[0]);
}

// ---------------- Phase 5: finalize
__global__ void k_final(float* out) {
    int nv = g_nvalid;
    if (nv < 1) nv = 1;
    out[0] = (float)(g_sum / (double)nv);
}

extern "C" void kernel_launch(void* const* d_in, const int* in_sizes, int n_in,
                              void* d_out, int out_size) {
    const float* img = (const float*)d_in[0];
    const float* txt = (const float*)d_in[1];
    const int*   key = (const int*)d_in[2];
    const float* sc  = (const float*)d_in[3];
    const float* bi  = (const float*)d_in[4];
    int s = in_sizes[2];          // 65536
    int n = in_sizes[1] / D;      // 8192

    k_init<<<(n + 255) / 256, 256>>>(n);
    k_norm_txt<<<(n * 32 + 255) / 256, 256>>>(txt, n);
    k_img<<<(s * 32 + 255) / 256, 256>>>(img, key, sc, bi, s);
    k_gather<<<(n * 32 + 255) / 256, 256>>>(img, n);
    dim3 grid(n / 128, n / 128);
    k_gemm_loss<<<grid, 256>>>(sc, bi, n);
    k_final<<<1, 1>>>((float*)d_out);
}

// round 4
// speedup vs baseline: 3.1724x; 3.0932x over previous
#include <cuda_runtime.h>
#include <cuda_bf16.h>
#include <math.h>
#include <stdint.h>

#define D 128
#define MAXS 65536
#define MAXN 8192

// ---------------- scratch (device globals — no runtime allocation)
__device__ float g_ztxt[MAXN * D];               // normalized text features (fp32, for k_img)
__device__ __nv_bfloat16 g_Tb[MAXN * D];         // normalized text features (bf16, GEMM B)
__device__ __nv_bfloat16 g_Ab[MAXN * D];         // selected+normalized image rows (bf16, GEMM A)
__device__ float g_inv[MAXS];                    // 1/(||img||+1e-12)
__device__ unsigned long long g_seg[MAXN];       // packed (pot_bits<<32)|img_idx, atomicMin
__device__ float g_validf[MAXN];
__device__ int g_nvalid;
__device__ double g_sum;

__device__ __forceinline__ uint32_t smem_u32(const void* p) {
    uint32_t a;
    asm("{ .reg .u64 t; cvta.to.shared.u64 t, %1; cvt.u32.u64 %0, t; }" : "=r"(a) : "l"(p));
    return a;
}

// ---------------- Phase 0: reset scratch
__global__ void k_init(int n) {
    int i = blockIdx.x * blockDim.x + threadIdx.x;
    if (i < n) g_seg[i] = ~0ull;
    if (i == 0) { g_sum = 0.0; g_nvalid = 0; }
}

// ---------------- Phase 1: normalize text (one warp per row), fp32 + bf16 copies
__global__ void k_norm_txt(const float* __restrict__ txt, int n) {
    int w = (blockIdx.x * blockDim.x + threadIdx.x) >> 5;
    int lane = threadIdx.x & 31;
    if (w >= n) return;
    float4 v = reinterpret_cast<const float4*>(txt + (size_t)w * D)[lane];
    float ss = v.x*v.x + v.y*v.y + v.z*v.z + v.w*v.w;
    #pragma unroll
    for (int o = 16; o > 0; o >>= 1) ss += __shfl_xor_sync(0xffffffffu, ss, o);
    float inv = 1.0f / (sqrtf(ss) + 1e-12f);
    float4 r = make_float4(v.x*inv, v.y*inv, v.z*inv, v.w*inv);
    reinterpret_cast<float4*>(g_ztxt + (size_t)w * D)[lane] = r;
    __nv_bfloat162 b0 = __floats2bfloat162_rn(r.x, r.y);
    __nv_bfloat162 b1 = __floats2bfloat162_rn(r.z, r.w);
    __nv_bfloat162* dst = reinterpret_cast<__nv_bfloat162*>(g_Tb + (size_t)w * D + lane * 4);
    dst[0] = b0; dst[1] = b1;
}

// ---------------- Phase 2: tp logit + segmented argmin (precise fp32 selection)
__global__ void k_img(const float* __restrict__ img, const int* __restrict__ key,
                      const float* __restrict__ sp, const float* __restrict__ bp, int s) {
    int w = (blockIdx.x * blockDim.x + threadIdx.x) >> 5;
    int lane = threadIdx.x & 31;
    if (w >= s) return;
    float4 v = reinterpret_cast<const float4*>(img + (size_t)w * D)[lane];
    int k = key[w];
    float4 t = reinterpret_cast<const float4*>(g_ztxt + (size_t)k * D)[lane];
    float ss = v.x*v.x + v.y*v.y + v.z*v.z + v.w*v.w;
    float dt = v.x*t.x + v.y*t.y + v.z*t.z + v.w*t.w;
    #pragma unroll
    for (int o = 16; o > 0; o >>= 1) {
        ss += __shfl_xor_sync(0xffffffffu, ss, o);
        dt += __shfl_xor_sync(0xffffffffu, dt, o);
    }
    if (lane == 0) {
        float inv = 1.0f / (sqrtf(ss) + 1e-12f);
        g_inv[w] = inv;
        float tp = fmaf(dt * inv, *sp, *bp);
        float t0 = -tp;
        float pot = fmaxf(t0, 0.0f) + log1pf(expf(-fabsf(t0)));
        unsigned long long pk =
            ((unsigned long long)__float_as_uint(pot) << 32) | (unsigned)w;
        atomicMin(&g_seg[k], pk);
    }
}

// ---------------- Phase 3: gather best image per text -> bf16 A rows
__global__ void k_gather(const float* __restrict__ img, int n) {
    int w = (blockIdx.x * blockDim.x + threadIdx.x) >> 5;
    int lane = threadIdx.x & 31;
    if (w >= n) return;
    unsigned long long sv = g_seg[w];
    bool valid = (sv != ~0ull);
    float4 o = make_float4(0.f, 0.f, 0.f, 0.f);
    if (valid) {
        unsigned best = (unsigned)(sv & 0xffffffffu);
        float inv = g_inv[best];
        float4 v = reinterpret_cast<const float4*>(img + (size_t)best * D)[lane];
        o = make_float4(v.x*inv, v.y*inv, v.z*inv, v.w*inv);
    }
    __nv_bfloat162 b0 = __floats2bfloat162_rn(o.x, o.y);
    __nv_bfloat162 b1 = __floats2bfloat162_rn(o.z, o.w);
    __nv_bfloat162* dst = reinterpret_cast<__nv_bfloat162*>(g_Ab + (size_t)w * D + lane * 4);
    dst[0] = b0; dst[1] = b1;
    if (lane == 0) {
        g_validf[w] = valid ? 1.0f : 0.0f;
        if (valid) atomicAdd(&g_nvalid, 1);
    }
}

// ---------------- Phase 4: bf16 mma.sync GEMM (128x128 CTA tile, K=128) + fused loss
// 8 warps in 4(M) x 2(N); warp tile 32x64; atoms m16n8k16.
// SMEM layout: [0:32768) A tile, [32768:65536) B tile, then valid arrays + reduction.
__device__ __forceinline__ void ldsm4(uint32_t* r, uint32_t addr) {
    asm volatile("ldmatrix.sync.aligned.m8n8.x4.shared.b16 {%0,%1,%2,%3}, [%4];"
                 : "=r"(r[0]), "=r"(r[1]), "=r"(r[2]), "=r"(r[3]) : "r"(addr));
}
__device__ __forceinline__ void mma16816(float* c, const uint32_t* a, const uint32_t* b) {
    asm volatile("mma.sync.aligned.m16n8k16.row.col.f32.bf16.bf16.f32 "
                 "{%0,%1,%2,%3}, {%4,%5,%6,%7}, {%8,%9}, {%0,%1,%2,%3};"
                 : "+f"(c[0]), "+f"(c[1]), "+f"(c[2]), "+f"(c[3])
                 : "r"(a[0]), "r"(a[1]), "r"(a[2]), "r"(a[3]), "r"(b[0]), "r"(b[1]));
}
// swizzled byte offset inside a 128x256B tile: chunk cb (0..15) xored with row&7
__device__ __forceinline__ uint32_t sw_off(int row, int cb) {
    return (uint32_t)(row * 256 + (((cb ^ (row & 7)) & 15) << 4));
}

__global__ void __launch_bounds__(256)
k_gemm_loss(const float* __restrict__ sp, const float* __restrict__ bp, int n) {
    extern __shared__ __align__(1024) char smem[];
    const uint32_t A_OFF = 0u, B_OFF = 32768u;
    float* svr  = (float*)(smem + 65536);          // row valid (128)
    float* svc  = (float*)(smem + 65536 + 512);    // col valid (128)
    float* swred = (float*)(smem + 65536 + 1024);  // 8 warp partials
    uint32_t sb = smem_u32(smem);

    int tid = threadIdx.x, wid = tid >> 5, lane = tid & 31;
    int bm = blockIdx.y, bn = blockIdx.x;
    int wm = (wid & 3) << 5;   // warp M offset 0/32/64/96
    int wn = (wid >> 2) << 6;  // warp N offset 0/64

    if (tid < 128) svr[tid] = g_validf[bm * 128 + tid];
    else           svc[tid - 128] = g_validf[bn * 128 + (tid - 128)];

    // fill both tiles (row-major bf16 -> swizzled smem)
    const uint4* Ag = reinterpret_cast<const uint4*>(g_Ab + (size_t)bm * 128 * D);
    const uint4* Bg = reinterpret_cast<const uint4*>(g_Tb + (size_t)bn * 128 * D);
    #pragma unroll
    for (int i = 0; i < 8; i++) {
        int ch = tid + i * 256;          // 0..2047 16B chunks
        int row = ch >> 4, cb = ch & 15;
        uint32_t off = sw_off(row, cb);
        *reinterpret_cast<uint4*>(smem + A_OFF + off) = Ag[ch];
        *reinterpret_cast<uint4*>(smem + B_OFF + off) = Bg[ch];
    }
    __syncthreads();

    float acc[2][8][4];
    #pragma unroll
    for (int i = 0; i < 2; i++)
        #pragma unroll
        for (int j = 0; j < 8; j++)
            #pragma unroll
            for (int k = 0; k < 4; k++) acc[i][j][k] = 0.f;

    int lrow = lane & 15;        // ldmatrix row-within-16
    int lcb  = lane >> 4;        // ldmatrix chunk select (0/1)

    #pragma unroll
    for (int ks = 0; ks < 8; ks++) {
        int cb = ks * 2 + lcb;
        uint32_t af[2][4], bf[4][4];
        #pragma unroll
        for (int am = 0; am < 2; am++) {
            int row = wm + am * 16 + lrow;
            ldsm4(af[am], sb + A_OFF + sw_off(row, cb));
        }
        #pragma unroll
        for (int nb = 0; nb < 4; nb++) {
            int row = wn + nb * 16 + lrow;
            ldsm4(bf[nb], sb + B_OFF + sw_off(row, cb));
        }
        #pragma unroll
        for (int am = 0; am < 2; am++) {
            #pragma unroll
            for (int nb = 0; nb < 4; nb++) {
                uint32_t b0[2] = { bf[nb][0], bf[nb][2] };   // n-atom nb*2
                uint32_t b1[2] = { bf[nb][1], bf[nb][3] };   // n-atom nb*2+1
                mma16816(acc[am][nb * 2 + 0], af[am], b0);
                mma16816(acc[am][nb * 2 + 1], af[am], b1);
            }
        }
    }

    // ---------------- fused epilogue on register accumulators
    const float scale = *sp, bias = *bp;
    int qr = lane >> 2;          // quad row 0..7
    int qc = (lane & 3) << 1;    // quad col pair base
    float lsum = 0.f;
    #pragma unroll
    for (int am = 0; am < 2; am++) {
        int r0 = wm + am * 16 + qr;
        #pragma unroll
        for (int ci = 0; ci < 2; ci++) {       // row offset 0 / +8
            int lr = r0 + ci * 8;
            int gi = bm * 128 + lr;
            float vr = svr[lr];
            float rsum = 0.f;
            #pragma unroll
            for (int na = 0; na < 8; na++) {
                #pragma unroll
                for (int cj = 0; cj < 2; cj++) {
                    int lc = wn + na * 8 + qc + cj;
                    int gj = bn * 128 + lc;
                    float dv = acc[am][na][ci * 2 + cj];
                    float x = fmaf(dv, scale, bias);       // logit
                    float t = (gi == gj) ? -x : x;
                    float m = fmaxf(t, 0.f);
                    float r = __expf(-fabsf(t));
                    float spv;
                    if (r < 0.25f) {
                        spv = fmaf(r, fmaf(r, fmaf(r, fmaf(r, fmaf(r, 0.2f, -0.25f),
                                  0.33333334f), -0.5f), 1.0f), m);
                    } else {
                        spv = m + log1pf(r);
                    }
                    rsum = fmaf(spv, svc[lc], rsum);
                }
            }
            lsum = fmaf(rsum, vr, lsum);
        }
    }
    #pragma unroll
    for (int o = 16; o > 0; o >>= 1) lsum += __shfl_xor_sync(0xffffffffu, lsum, o);
    if (lane == 0) swred[wid] = lsum;
    __syncthreads();
    if (wid == 0) {
        float v = (lane < 8) ? swred[lane] : 0.f;
        #pragma unroll
        for (int o = 4; o > 0; o >>= 1) v += __shfl_xor_sync(0xffffffffu, v, o);
        if (lane == 0) atomicAdd(&g_sum, (double)v);
    }
}

// ---------------- Phase 5: finalize
__global__ void k_final(float* out) {
    int nv = g_nvalid;
    if (nv < 1) nv = 1;
    out[0] = (float)(g_sum / (double)nv);
}

extern "C" void kernel_launch(void* const* d_in, const int* in_sizes, int n_in,
                              void* d_out, int out_size) {
    const float* img = (const float*)d_in[0];
    const float* txt = (const float*)d_in[1];
    const int*   key = (const int*)d_in[2];
    const float* sc  = (const float*)d_in[3];
    const float* bi  = (const float*)d_in[4];
    int s = in_sizes[2];          // 65536
    int n = in_sizes[1] / D;      // 8192

    const int SMEM_BYTES = 65536 + 1024 + 64;
    cudaFuncSetAttribute(k_gemm_loss, cudaFuncAttributeMaxDynamicSharedMemorySize, SMEM_BYTES);

    k_init<<<(n + 255) / 256, 256>>>(n);
    k_norm_txt<<<(n * 32 + 255) / 256, 256>>>(txt, n);
    k_img<<<(s * 32 + 255) / 256, 256>>>(img, key, sc, bi, s);
    k_gather<<<(n * 32 + 255) / 256, 256>>>(img, n);
    dim3 grid(n / 128, n / 128);
    k_gemm_loss<<<grid, 256, SMEM_BYTES>>>(sc, bi, n);
    k_final<<<1, 1>>>((float*)d_out);
}

// round 5
// speedup vs baseline: 5.1517x; 1.6239x over previous
#include <cuda_runtime.h>
#include <cuda_bf16.h>
#include <math.h>
#include <stdint.h>

#define D 128
#define MAXS 65536
#define MAXN 8192

// ---------------- scratch (device globals — no runtime allocation)
__device__ float g_ztxt[MAXN * D];               // normalized text features (fp32, for k_img)
__device__ __nv_bfloat16 g_Tb[MAXN * D];         // normalized text features (bf16)
__device__ __nv_bfloat16 g_TbM[MAXN * D];        // col-masked bf16 text features (GEMM B)
__device__ __nv_bfloat16 g_Ab[MAXN * D];         // selected+normalized image rows (GEMM A)
__device__ float g_inv[MAXS];                    // 1/(||img||+1e-12)
__device__ unsigned long long g_seg[MAXN];       // packed (pot_bits<<32)|img_idx, atomicMin
__device__ int g_nvalid;
__device__ double g_sum;

__device__ __forceinline__ uint32_t smem_u32(const void* p) {
    uint32_t a;
    asm("{ .reg .u64 t; cvta.to.shared.u64 t, %1; cvt.u32.u64 %0, t; }" : "=r"(a) : "l"(p));
    return a;
}

// ---------------- Phase 1: normalize text (warp/row) + fused scratch init
__global__ void k_norm_txt(const float* __restrict__ txt, int n) {
    int gtid = blockIdx.x * blockDim.x + threadIdx.x;
    if (gtid < n) g_seg[gtid] = ~0ull;
    if (gtid == 0) { g_sum = 0.0; g_nvalid = 0; }
    int w = gtid >> 5;
    int lane = threadIdx.x & 31;
    if (w >= n) return;
    float4 v = reinterpret_cast<const float4*>(txt + (size_t)w * D)[lane];
    float ss = v.x*v.x + v.y*v.y + v.z*v.z + v.w*v.w;
    #pragma unroll
    for (int o = 16; o > 0; o >>= 1) ss += __shfl_xor_sync(0xffffffffu, ss, o);
    float inv = 1.0f / (sqrtf(ss) + 1e-12f);
    float4 r = make_float4(v.x*inv, v.y*inv, v.z*inv, v.w*inv);
    reinterpret_cast<float4*>(g_ztxt + (size_t)w * D)[lane] = r;
    __nv_bfloat162 b0 = __floats2bfloat162_rn(r.x, r.y);
    __nv_bfloat162 b1 = __floats2bfloat162_rn(r.z, r.w);
    __nv_bfloat162* dst = reinterpret_cast<__nv_bfloat162*>(g_Tb + (size_t)w * D + lane * 4);
    dst[0] = b0; dst[1] = b1;
}

// ---------------- Phase 2: tp logit + segmented argmin (precise fp32 selection)
__global__ void k_img(const float* __restrict__ img, const int* __restrict__ key,
                      const float* __restrict__ sp, const float* __restrict__ bp, int s) {
    int w = (blockIdx.x * blockDim.x + threadIdx.x) >> 5;
    int lane = threadIdx.x & 31;
    if (w >= s) return;
    float4 v = reinterpret_cast<const float4*>(img + (size_t)w * D)[lane];
    int k = key[w];
    float4 t = reinterpret_cast<const float4*>(g_ztxt + (size_t)k * D)[lane];
    float ss = v.x*v.x + v.y*v.y + v.z*v.z + v.w*v.w;
    float dt = v.x*t.x + v.y*t.y + v.z*t.z + v.w*t.w;
    #pragma unroll
    for (int o = 16; o > 0; o >>= 1) {
        ss += __shfl_xor_sync(0xffffffffu, ss, o);
        dt += __shfl_xor_sync(0xffffffffu, dt, o);
    }
    if (lane == 0) {
        float inv = 1.0f / (sqrtf(ss) + 1e-12f);
        g_inv[w] = inv;
        float tp = fmaf(dt * inv, *sp, *bp);
        float t0 = -tp;
        float pot = fmaxf(t0, 0.0f) + log1pf(expf(-fabsf(t0)));
        unsigned long long pk =
            ((unsigned long long)__float_as_uint(pot) << 32) | (unsigned)w;
        atomicMin(&g_seg[k], pk);
    }
}

// ---------------- Phase 3: gather best image -> bf16 A rows; write col-masked B
__global__ void k_gather(const float* __restrict__ img, int n) {
    int w = (blockIdx.x * blockDim.x + threadIdx.x) >> 5;
    int lane = threadIdx.x & 31;
    if (w >= n) return;
    unsigned long long sv = g_seg[w];
    bool valid = (sv != ~0ull);
    float4 o = make_float4(0.f, 0.f, 0.f, 0.f);
    if (valid) {
        unsigned best = (unsigned)(sv & 0xffffffffu);
        float inv = g_inv[best];
        float4 v = reinterpret_cast<const float4*>(img + (size_t)best * D)[lane];
        o = make_float4(v.x*inv, v.y*inv, v.z*inv, v.w*inv);
    }
    __nv_bfloat162 b0 = __floats2bfloat162_rn(o.x, o.y);
    __nv_bfloat162 b1 = __floats2bfloat162_rn(o.z, o.w);
    __nv_bfloat162* dst = reinterpret_cast<__nv_bfloat162*>(g_Ab + (size_t)w * D + lane * 4);
    dst[0] = b0; dst[1] = b1;
    // col-masked B copy: zero the whole text row if this text has no image
    uint2 tv = make_uint2(0u, 0u);
    if (valid)
        tv = reinterpret_cast<const uint2*>(g_Tb + (size_t)w * D)[lane];
    reinterpret_cast<uint2*>(g_TbM + (size_t)w * D)[lane] = tv;
    if (lane == 0 && valid) atomicAdd(&g_nvalid, 1);
}

// ---------------- Phase 4: bf16 mma.sync GEMM (128x128 CTA tile) + fused loss
__device__ __forceinline__ void ldsm4(uint32_t* r, uint32_t addr) {
    asm volatile("ldmatrix.sync.aligned.m8n8.x4.shared.b16 {%0,%1,%2,%3}, [%4];"
                 : "=r"(r[0]), "=r"(r[1]), "=r"(r[2]), "=r"(r[3]) : "r"(addr));
}
__device__ __forceinline__ void mma16816(float* c, const uint32_t* a, const uint32_t* b) {
    asm volatile("mma.sync.aligned.m16n8k16.row.col.f32.bf16.bf16.f32 "
                 "{%0,%1,%2,%3}, {%4,%5,%6,%7}, {%8,%9}, {%0,%1,%2,%3};"
                 : "+f"(c[0]), "+f"(c[1]), "+f"(c[2]), "+f"(c[3])
                 : "r"(a[0]), "r"(a[1]), "r"(a[2]), "r"(a[3]), "r"(b[0]), "r"(b[1]));
}
__device__ __forceinline__ uint32_t sw_off(int row, int cb) {
    return (uint32_t)(row * 256 + (((cb ^ (row & 7)) & 15) << 4));
}

__global__ void __launch_bounds__(256)
k_gemm_loss(const float* __restrict__ sp, const float* __restrict__ bp) {
    extern __shared__ __align__(1024) char smem[];
    const uint32_t A_OFF = 0u, B_OFF = 32768u;
    float* swred = (float*)(smem + 65536);
    uint32_t sb = smem_u32(smem);

    int tid = threadIdx.x, wid = tid >> 5, lane = tid & 31;
    int bm = blockIdx.y, bn = blockIdx.x;
    int wm = (wid & 3) << 5;   // warp M offset
    int wn = (wid >> 2) << 6;  // warp N offset

    const uint4* Ag = reinterpret_cast<const uint4*>(g_Ab  + (size_t)bm * 128 * D);
    const uint4* Bg = reinterpret_cast<const uint4*>(g_TbM + (size_t)bn * 128 * D);
    #pragma unroll
    for (int i = 0; i < 8; i++) {
        int ch = tid + i * 256;
        int row = ch >> 4, cb = ch & 15;
        uint32_t off = sw_off(row, cb);
        *reinterpret_cast<uint4*>(smem + A_OFF + off) = Ag[ch];
        *reinterpret_cast<uint4*>(smem + B_OFF + off) = Bg[ch];
    }
    __syncthreads();

    float acc[2][8][4];
    #pragma unroll
    for (int i = 0; i < 2; i++)
        #pragma unroll
        for (int j = 0; j < 8; j++)
            #pragma unroll
            for (int k = 0; k < 4; k++) acc[i][j][k] = 0.f;

    int lrow = lane & 15;
    int lcb  = lane >> 4;

    #pragma unroll
    for (int ks = 0; ks < 8; ks++) {
        int cb = ks * 2 + lcb;
        uint32_t af[2][4], bf[4][4];
        #pragma unroll
        for (int am = 0; am < 2; am++)
            ldsm4(af[am], sb + A_OFF + sw_off(wm + am * 16 + lrow, cb));
        #pragma unroll
        for (int nb = 0; nb < 4; nb++)
            ldsm4(bf[nb], sb + B_OFF + sw_off(wn + nb * 16 + lrow, cb));
        #pragma unroll
        for (int am = 0; am < 2; am++) {
            #pragma unroll
            for (int nb = 0; nb < 4; nb++) {
                uint32_t b0[2] = { bf[nb][0], bf[nb][2] };
                uint32_t b1[2] = { bf[nb][1], bf[nb][3] };
                mma16816(acc[am][nb * 2 + 0], af[am], b0);
                mma16816(acc[am][nb * 2 + 1], af[am], b1);
            }
        }
    }

    // ---------------- fused epilogue: softplus(logit) summed, diag adjusted
    const float scale = *sp, bias = *bp;
    const float sl = scale * 1.44269504f, bl = bias * 1.44269504f;
    int qr = lane >> 2;
    int qc = (lane & 3) << 1;
    float lsum = 0.f;
    if (bm != bn) {
        #pragma unroll
        for (int am = 0; am < 2; am++)
            #pragma unroll
            for (int na = 0; na < 8; na++)
                #pragma unroll
                for (int k = 0; k < 4; k++) {
                    float dv = acc[am][na][k];
                    float x2 = fmaf(dv, sl, bl);
                    float r; asm("ex2.approx.f32 %0, %1;" : "=f"(r) : "f"(x2));
                    float p = fmaf(r, fmaf(r, 0.33333334f, -0.5f), 1.0f);
                    lsum = fmaf(r, p, lsum);      // += log1p(e^x) ≈ softplus(x)
                }
    } else {
        #pragma unroll
        for (int am = 0; am < 2; am++) {
            #pragma unroll
            for (int na = 0; na < 8; na++) {
                #pragma unroll
                for (int k = 0; k < 4; k++) {
                    int ci = k >> 1, cj = k & 1;
                    int lr = wm + am * 16 + qr + ci * 8;
                    int lc = wn + na * 8 + qc + cj;
                    float dv = acc[am][na][k];
                    float x2 = fmaf(dv, sl, bl);
                    float r; asm("ex2.approx.f32 %0, %1;" : "=f"(r) : "f"(x2));
                    float p = fmaf(r, fmaf(r, 0.33333334f, -0.5f), 1.0f);
                    lsum = fmaf(r, p, lsum);
                    if (lr == lc)                  // softplus(-x) = softplus(x) - x
                        lsum -= fmaf(dv, scale, bias);
                }
            }
        }
    }
    #pragma unroll
    for (int o = 16; o > 0; o >>= 1) lsum += __shfl_xor_sync(0xffffffffu, lsum, o);
    if (lane == 0) swred[wid] = lsum;
    __syncthreads();
    if (wid == 0) {
        float v = (lane < 8) ? swred[lane] : 0.f;
        #pragma unroll
        for (int o = 4; o > 0; o >>= 1) v += __shfl_xor_sync(0xffffffffu, v, o);
        if (lane == 0) atomicAdd(&g_sum, (double)v);
    }
}

// ---------------- Phase 5: finalize with analytic invalid-pair correction
__global__ void k_final(float* out, const float* __restrict__ bp, int n) {
    float bias = *bp;
    int nv = g_nvalid;
    int n_inv = n - nv;
    // c0 = series softplus at dv=0, matching GEMM arithmetic
    float bl = bias * 1.44269504f;
    float r0; asm("ex2.approx.f32 %0, %1;" : "=f"(r0) : "f"(bl));
    float p0 = fmaf(r0, fmaf(r0, 0.33333334f, -0.5f), 1.0f);
    double c0 = (double)r0 * (double)p0;
    double npairs_inv = (double)n * (double)n - (double)nv * (double)nv;
    double corr = npairs_inv * c0 - (double)n_inv * (double)bias;
    int dnv = nv < 1 ? 1 : nv;
    out[0] = (float)((g_sum - corr) / (double)dnv);
}

extern "C" void kernel_launch(void* const* d_in, const int* in_sizes, int n_in,
                              void* d_out, int out_size) {
    const float* img = (const float*)d_in[0];
    const float* txt = (const float*)d_in[1];
    const int*   key = (const int*)d_in[2];
    const float* sc  = (const float*)d_in[3];
    const float* bi  = (const float*)d_in[4];
    int s = in_sizes[2];          // 65536
    int n = in_sizes[1] / D;      // 8192

    const int SMEM_BYTES = 65536 + 64;
    cudaFuncSetAttribute(k_gemm_loss, cudaFuncAttributeMaxDynamicSharedMemorySize, SMEM_BYTES);

    k_norm_txt<<<(n * 32 + 255) / 256, 256>>>(txt, n);
    k_img<<<(s * 32 + 255) / 256, 256>>>(img, key, sc, bi, s);
    k_gather<<<(n * 32 + 255) / 256, 256>>>(img, n);
    dim3 grid(n / 128, n / 128);
    k_gemm_loss<<<grid, 256, SMEM_BYTES>>>(sc, bi);
    k_final<<<1, 1>>>((float*)d_out, bi, n);
}